// round 9
// baseline (speedup 1.0000x reference)
#include <cuda_runtime.h>
#include <cstdint>

#define NPTS 4096
#define DDIM 64
#define SLD 132     // staging stride: conflict-free transpose staging (banks 8t+g)
#define NBLOCKS 272 // pair-tile blocks

// ---------------- device scratch (zero-init; counters self-reset) ----------------
__device__ float g_partial_sq[64];
__device__ float g_partial_col[64][64];
__device__ float g_c;
__device__ int   g_arrive = 0;
__device__ int   g_done   = 0;
__device__ unsigned int g_flag = 0;

__device__ __forceinline__ uint32_t to_tf32(float f) {
    uint32_t o; asm("cvt.rna.tf32.f32 %0, %1;" : "=r"(o) : "f"(f)); return o;
}

// ---- tf32 mma over one 128x128 tile; tiles are [128][64] paired-k + XOR swizzle ----
// element (row, k=8ks+t+4kh) lives at float offset row*64 + ((8ks+2t+kh) ^ ((row&3)<<3))
__device__ __forceinline__ void mma_tile(const float* As, const float* Bs,
                                         int warpRow, int warpCol, int g, int t,
                                         float acc[2][8][4]) {
#pragma unroll
    for (int m = 0; m < 2; m++)
#pragma unroll
        for (int n = 0; n < 8; n++)
#pragma unroll
            for (int j = 0; j < 4; j++) acc[m][n][j] = 0.f;
    const int gx = g & 3;
#pragma unroll
    for (int ks = 0; ks < 8; ks++) {
        const int ko = ((ks ^ gx) << 3) + (t << 1);
        uint32_t af[2][4], bf[8][2];
#pragma unroll
        for (int m = 0; m < 2; m++) {
            const float* ap = As + (size_t)(warpRow + (m << 4) + g) * 64 + ko;
            float2 x0 = *(const float2*)ap;            // (row, t), (row, t+4)
            float2 x1 = *(const float2*)(ap + 512);    // (row+8, t), (row+8, t+4)
            af[m][0] = __float_as_uint(x0.x);
            af[m][1] = __float_as_uint(x1.x);
            af[m][2] = __float_as_uint(x0.y);
            af[m][3] = __float_as_uint(x1.y);
        }
#pragma unroll
        for (int n = 0; n < 8; n++) {
            float2 b2 = *(const float2*)(Bs + (size_t)(warpCol + (n << 3) + g) * 64 + ko);
            bf[n][0] = __float_as_uint(b2.x);
            bf[n][1] = __float_as_uint(b2.y);
        }
#pragma unroll
        for (int m = 0; m < 2; m++)
#pragma unroll
            for (int n = 0; n < 8; n++) {
                asm volatile(
                    "mma.sync.aligned.m16n8k8.row.col.f32.tf32.tf32.f32 "
                    "{%0,%1,%2,%3}, {%4,%5,%6,%7}, {%8,%9}, {%0,%1,%2,%3};"
                    : "+f"(acc[m][n][0]), "+f"(acc[m][n][1]),
                      "+f"(acc[m][n][2]), "+f"(acc[m][n][3])
                    : "r"(af[m][0]), "r"(af[m][1]), "r"(af[m][2]), "r"(af[m][3]),
                      "r"(bf[n][0]), "r"(bf[n][1]));
            }
    }
}

__device__ __forceinline__ void epilogue_tile(float acc[2][8][4],
                                              const float* sqa, const float* sqb,
                                              float cc, float* out,
                                              int rowBase, int colBase,
                                              int warpRow, int warpCol, int g, int t,
                                              bool stage, float* stg) {
    const float c2 = 2.f * cc;
#pragma unroll
    for (int m = 0; m < 2; m++) {
        const int r0 = warpRow + (m << 4) + g;
        const float u0 = -cc * sqa[r0], u1 = -cc * sqa[r0 + 8];
#pragma unroll
        for (int n = 0; n < 8; n++) {
            const int c0 = warpCol + (n << 3) + (t << 1);
            const float v0 = -cc * sqb[c0], v1 = -cc * sqb[c0 + 1];
            const float ws[4] = { u0 + v0, u0 + v1, u1 + v0, u1 + v1 };
            float r[4];
#pragma unroll
            for (int j = 0; j < 4; j++) {
                float y = fminf(fmaf(c2, acc[m][n][j], ws[j]), 0.f);
                float e;
                asm("ex2.approx.ftz.f32 %0, %1;" : "=f"(e) : "f"(y));
                float e2 = e * e, e4 = e2 * e2, e8 = e4 * e4, e16 = e8 * e8;
                r[j] = e + e2 + e4 + e8 + e16;
            }
            float* o0 = out + (size_t)(rowBase + r0) * NPTS + colBase + c0;
            float* o1 = out + (size_t)(rowBase + r0 + 8) * NPTS + colBase + c0;
            *(float2*)o0 = make_float2(r[0], r[1]);
            *(float2*)o1 = make_float2(r[2], r[3]);
            if (stage) {
                stg[(c0)     * SLD + r0]     = r[0];
                stg[(c0 + 1) * SLD + r0]     = r[1];
                stg[(c0)     * SLD + r0 + 8] = r[2];
                stg[(c0 + 1) * SLD + r0 + 8] = r[3];
            }
        }
    }
}

__device__ __forceinline__ void mirror_tile(const float* stg, float* out,
                                            int rowBase, int colBase,
                                            int wid, int lane) {
    const int c_off = lane >> 3, r_off = (lane & 7) << 2;
#pragma unroll
    for (int i = 0; i < 16; i++) {
        int c = (wid << 4) + ((i & 3) << 2) + c_off;
        int r = ((i >> 2) << 5) + r_off;
        float4 v = *(const float4*)&stg[c * SLD + r];
        *(float4*)(out + (size_t)(colBase + c) * NPTS + rowBase + r) = v;
    }
}

// permute a loaded float4 (k = 4f..4f+3) into the paired-k quad for this thread
__device__ __forceinline__ uint4 perm_quad(float4 v, int kh) {
    float sA = kh ? v.x : v.z;
    float sB = kh ? v.y : v.w;
    float rA = __shfl_xor_sync(0xffffffffu, sA, 1);
    float rB = __shfl_xor_sync(0xffffffffu, sB, 1);
    uint4 q;
    if (kh == 0) {
        q.x = to_tf32(v.x); q.y = to_tf32(rA); q.z = to_tf32(v.y); q.w = to_tf32(rB);
    } else {
        q.x = to_tf32(rA);  q.y = to_tf32(v.z); q.z = to_tf32(rB); q.w = to_tf32(v.w);
    }
    return q;
}

__global__ __launch_bounds__(256, 2)
void rbf_fused_kernel(const float* __restrict__ X, float* __restrict__ out) {
    extern __shared__ float smem[];
    float* As  = smem;                  // [128][64] swizzled
    float* B1s = smem + 8192;
    float* B2s = smem + 16384;
    float* stg = smem + 8192;           // aliases B1s+B2s (+512 extra floats)
    __shared__ float sqa[128], sqb1[128], sqb2[128];
    __shared__ float red[256];
    __shared__ float colp[8][64];
    __shared__ float s_c;
    __shared__ int   s_last;

    const int tid = threadIdx.x;
    const int wid = tid >> 5, lane = tid & 31;
    const int bid = blockIdx.x;

    // pair-tile decode: bid -> (bi, p); tiles (bi, 2p) [if valid] and (bi, 2p+1)
    int bi = 0, rr = bid;
    while (rr >= 16 - (bi >> 1)) { rr -= 16 - (bi >> 1); bi++; }
    const int p = (bi >> 1) + rr;
    const bool two = (2 * p >= bi);
    const int bj1 = two ? 2 * p : 2 * p + 1;
    const int bj2 = 2 * p + 1;
    const bool diag1 = (bj1 == bi);
    const int rowBase = bi << 7, colBase1 = bj1 << 7, colBase2 = bj2 << 7;

    // ================= phase 0: bandwidth reduction duty (bid < 64) =================
    if (bid < 64) {
        const int rrow = (bid << 6) + (tid >> 2);
        const int q = tid & 3;
        float v[16];
        const float4* pp = (const float4*)(X + (size_t)rrow * DDIM + q * 16);
        float s = 0.f;
#pragma unroll
        for (int i = 0; i < 4; i++) {
            float4 f = pp[i];
            v[i * 4 + 0] = f.x; v[i * 4 + 1] = f.y; v[i * 4 + 2] = f.z; v[i * 4 + 3] = f.w;
            s += f.x * f.x + f.y * f.y + f.z * f.z + f.w * f.w;
        }
        red[tid] = s;
        __syncthreads();
#pragma unroll
        for (int off = 128; off > 0; off >>= 1) {
            if (tid < off) red[tid] += red[tid + off];
            __syncthreads();
        }
        if (tid == 0) g_partial_sq[bid] = red[0];
#pragma unroll
        for (int stp = 4; stp <= 16; stp <<= 1)
#pragma unroll
            for (int i = 0; i < 16; i++)
                v[i] += __shfl_xor_sync(0xffffffffu, v[i], stp);
        if (lane < 4) {
#pragma unroll
            for (int i = 0; i < 16; i++) colp[wid][lane * 16 + i] = v[i];
        }
        __syncthreads();
        if (tid < 64) {
            float t = 0.f;
#pragma unroll
            for (int w = 0; w < 8; w++) t += colp[w][tid];
            g_partial_col[bid][tid] = t;
        }
        __threadfence();
        if (tid == 0) {
            int r = atomicAdd(&g_arrive, 1);
            s_last = (r == 63);
        }
        __syncthreads();
        if (s_last) {
            if (tid < 64) {
                float cs = 0.f;
#pragma unroll
                for (int b = 0; b < 64; b++) cs += g_partial_col[b][tid];
                red[tid] = cs * cs;
                red[128 + tid] = g_partial_sq[tid];
            }
            __syncthreads();
#pragma unroll
            for (int off = 32; off > 0; off >>= 1) {
                if (tid < off) { red[tid] += red[tid + off]; red[128 + tid] += red[128 + tid + off]; }
                __syncthreads();
            }
            if (tid == 0) {
                // sum(L2) = 2*N*sum(||xi||^2) - 2*||sum xi||^2 (clamp negligible)
                float bwsum = 2.f * (float)NPTS * red[128] - 2.f * red[0];
                float bw = bwsum / ((float)NPTS * (float)(NPTS - 1));
                g_c = 1.4426950408889634f / (4.f * bw);
                __threadfence();
                asm volatile("st.release.gpu.b32 [%0], %1;" :: "l"(&g_flag), "r"(1u) : "memory");
            }
        }
        __syncthreads();
    }

    // ================= phase 1: fill A + B1 tiles (paired-k tf32) + norms =================
#pragma unroll
    for (int i = 0; i < 8; i++) {
        int idx = tid + (i << 8);
        int r = idx >> 4, f = idx & 15;
        float4 va = *(const float4*)(X + (size_t)(rowBase + r) * DDIM + (f << 2));
        float4 vb = *(const float4*)(X + (size_t)(colBase1 + r) * DDIM + (f << 2));
        float da = va.x * va.x + va.y * va.y + va.z * va.z + va.w * va.w;
        float db = vb.x * vb.x + vb.y * vb.y + vb.z * vb.z + vb.w * vb.w;
#pragma unroll
        for (int stp = 1; stp <= 8; stp <<= 1) {
            da += __shfl_xor_sync(0xffffffffu, da, stp);
            db += __shfl_xor_sync(0xffffffffu, db, stp);
        }
        if ((lane & 15) == 0) { sqa[r] = da; sqb1[r] = db; }
        const int kh = f & 1;
        uint4 qa = perm_quad(va, kh);
        uint4 qb = perm_quad(vb, kh);
        const int off = r * 64 + (((f << 2)) ^ ((r & 3) << 3));
        *(uint4*)(As + off) = qa;
        *(uint4*)(B1s + off) = qb;
    }
    __syncthreads();

    // ================= phase 2: MMA tile 1 =================
    const int g = lane >> 2, t = lane & 3;
    const int warpRow = (wid & 3) << 5;
    const int warpCol = (wid >> 2) << 6;

    float acc[2][8][4];
    mma_tile(As, B1s, warpRow, warpCol, g, t, acc);

    // prefetch B2 into registers (latency hides under spin + epilogue1)
    float4 pb[8];
    if (two) {
#pragma unroll
        for (int i = 0; i < 8; i++) {
            int idx = tid + (i << 8);
            int r = idx >> 4, f = idx & 15;
            pb[i] = *(const float4*)(X + (size_t)(colBase2 + r) * DDIM + (f << 2));
        }
    }

    // ================= phase 3: wait for g_c (usually already set) =================
    if (tid == 0) {
        unsigned int f;
        do {
            asm volatile("ld.acquire.gpu.b32 %0, [%1];" : "=r"(f) : "l"(&g_flag) : "memory");
        } while (f == 0);
        s_c = g_c;
    }
    __syncthreads();   // also: all MMA1 reads complete before stg writes
    const float cc = s_c;

    // ================= phase 4: epilogue tile 1 (+ mirror if offdiag) =================
    epilogue_tile(acc, sqa, sqb1, cc, out, rowBase, colBase1,
                  warpRow, warpCol, g, t, !diag1, stg);
    if (!diag1) {
        __syncthreads();
        mirror_tile(stg, out, rowBase, colBase1, wid, lane);
    }

    // ================= phase 5: tile 2 =================
    if (two) {
        __syncthreads();   // mirror1 stg reads done before B2s overwrite
#pragma unroll
        for (int i = 0; i < 8; i++) {
            int idx = tid + (i << 8);
            int r = idx >> 4, f = idx & 15;
            float4 vb = pb[i];
            float db = vb.x * vb.x + vb.y * vb.y + vb.z * vb.z + vb.w * vb.w;
#pragma unroll
            for (int stp = 1; stp <= 8; stp <<= 1)
                db += __shfl_xor_sync(0xffffffffu, db, stp);
            if ((lane & 15) == 0) sqb2[r] = db;
            const int kh = f & 1;
            uint4 qb = perm_quad(vb, kh);
            const int off = r * 64 + (((f << 2)) ^ ((r & 3) << 3));
            *(uint4*)(B2s + off) = qb;
        }
        __syncthreads();

        mma_tile(As, B2s, warpRow, warpCol, g, t, acc);
        __syncthreads();   // all B2s reads complete before stg writes

        epilogue_tile(acc, sqa, sqb2, cc, out, rowBase, colBase2,
                      warpRow, warpCol, g, t, true, stg);
        __syncthreads();
        mirror_tile(stg, out, rowBase, colBase2, wid, lane);
    }

    // ================= phase 6: last CTA resets counters for next replay =================
    if (tid == 0) {
        int d = atomicAdd(&g_done, 1);
        if (d == NBLOCKS - 1) {
            g_arrive = 0;
            g_done = 0;
            asm volatile("st.relaxed.gpu.b32 [%0], %1;" :: "l"(&g_flag), "r"(0u) : "memory");
        }
    }
}

// ---------------- launch ----------------
extern "C" void kernel_launch(void* const* d_in, const int* in_sizes, int n_in,
                              void* d_out, int out_size) {
    const float* X = (const float*)d_in[0];
    float* out = (float*)d_out;

    const int smem_bytes = (8192 + 16896) * sizeof(float);   // 100352
    cudaFuncSetAttribute(rbf_fused_kernel, cudaFuncAttributeMaxDynamicSharedMemorySize, smem_bytes);

    rbf_fused_kernel<<<NBLOCKS, 256, smem_bytes>>>(X, out);
}

// round 10
// speedup vs baseline: 1.0021x; 1.0021x over previous
#include <cuda_runtime.h>
#include <cstdint>

#define NPTS 4096
#define DDIM 64
#define SLD 132     // staging stride: conflict-free transpose staging (banks 8t+g)
#define NBLOCKS 272 // pair-tile blocks

// ---------------- device scratch (zero-init; counters self-reset) ----------------
__device__ float g_partial_sq[64];
__device__ float g_partial_col[64][64];
__device__ float g_c;
__device__ int   g_arrive = 0;
__device__ int   g_done   = 0;
__device__ unsigned int g_flag = 0;

__device__ __forceinline__ uint32_t to_tf32(float f) {
    uint32_t o; asm("cvt.rna.tf32.f32 %0, %1;" : "=r"(o) : "f"(f)); return o;
}

// ---- tf32 mma over one 128x128 tile; tiles are [128][64] paired-k + XOR swizzle ----
// element (row, k=8ks+t+4kh) lives at float offset row*64 + ((8ks+2t+kh) ^ ((row&3)<<3))
__device__ __forceinline__ void mma_tile(const float* As, const float* Bs,
                                         int warpRow, int warpCol, int g, int t,
                                         float acc[2][8][4]) {
#pragma unroll
    for (int m = 0; m < 2; m++)
#pragma unroll
        for (int n = 0; n < 8; n++)
#pragma unroll
            for (int j = 0; j < 4; j++) acc[m][n][j] = 0.f;
    const int gx = g & 3;
#pragma unroll
    for (int ks = 0; ks < 8; ks++) {
        const int ko = ((ks ^ gx) << 3) + (t << 1);
        uint32_t af[2][4], bf[8][2];
#pragma unroll
        for (int m = 0; m < 2; m++) {
            const float* ap = As + (size_t)(warpRow + (m << 4) + g) * 64 + ko;
            float2 x0 = *(const float2*)ap;            // (row, t), (row, t+4)
            float2 x1 = *(const float2*)(ap + 512);    // (row+8, t), (row+8, t+4)
            af[m][0] = __float_as_uint(x0.x);
            af[m][1] = __float_as_uint(x1.x);
            af[m][2] = __float_as_uint(x0.y);
            af[m][3] = __float_as_uint(x1.y);
        }
#pragma unroll
        for (int n = 0; n < 8; n++) {
            float2 b2 = *(const float2*)(Bs + (size_t)(warpCol + (n << 3) + g) * 64 + ko);
            bf[n][0] = __float_as_uint(b2.x);
            bf[n][1] = __float_as_uint(b2.y);
        }
#pragma unroll
        for (int m = 0; m < 2; m++)
#pragma unroll
            for (int n = 0; n < 8; n++) {
                asm volatile(
                    "mma.sync.aligned.m16n8k8.row.col.f32.tf32.tf32.f32 "
                    "{%0,%1,%2,%3}, {%4,%5,%6,%7}, {%8,%9}, {%0,%1,%2,%3};"
                    : "+f"(acc[m][n][0]), "+f"(acc[m][n][1]),
                      "+f"(acc[m][n][2]), "+f"(acc[m][n][3])
                    : "r"(af[m][0]), "r"(af[m][1]), "r"(af[m][2]), "r"(af[m][3]),
                      "r"(bf[n][0]), "r"(bf[n][1]));
            }
    }
}

__device__ __forceinline__ void epilogue_tile(float acc[2][8][4],
                                              const float* sqa, const float* sqb,
                                              float cc, float* out,
                                              int rowBase, int colBase,
                                              int warpRow, int warpCol, int g, int t,
                                              bool stage, float* stg) {
    const float c2 = 2.f * cc;
#pragma unroll
    for (int m = 0; m < 2; m++) {
        const int r0 = warpRow + (m << 4) + g;
        const float u0 = -cc * sqa[r0], u1 = -cc * sqa[r0 + 8];
#pragma unroll
        for (int n = 0; n < 8; n++) {
            const int c0 = warpCol + (n << 3) + (t << 1);
            const float v0 = -cc * sqb[c0], v1 = -cc * sqb[c0 + 1];
            const float ws[4] = { u0 + v0, u0 + v1, u1 + v0, u1 + v1 };
            float r[4];
#pragma unroll
            for (int j = 0; j < 4; j++) {
                float y = fminf(fmaf(c2, acc[m][n][j], ws[j]), 0.f);
                float e;
                asm("ex2.approx.ftz.f32 %0, %1;" : "=f"(e) : "f"(y));
                float e2 = e * e, e4 = e2 * e2, e8 = e4 * e4, e16 = e8 * e8;
                r[j] = e + e2 + e4 + e8 + e16;
            }
            float* o0 = out + (size_t)(rowBase + r0) * NPTS + colBase + c0;
            float* o1 = out + (size_t)(rowBase + r0 + 8) * NPTS + colBase + c0;
            *(float2*)o0 = make_float2(r[0], r[1]);
            *(float2*)o1 = make_float2(r[2], r[3]);
            if (stage) {
                stg[(c0)     * SLD + r0]     = r[0];
                stg[(c0 + 1) * SLD + r0]     = r[1];
                stg[(c0)     * SLD + r0 + 8] = r[2];
                stg[(c0 + 1) * SLD + r0 + 8] = r[3];
            }
        }
    }
}

__device__ __forceinline__ void mirror_tile(const float* stg, float* out,
                                            int rowBase, int colBase,
                                            int wid, int lane) {
    const int c_off = lane >> 3, r_off = (lane & 7) << 2;
#pragma unroll
    for (int i = 0; i < 16; i++) {
        int c = (wid << 4) + ((i & 3) << 2) + c_off;
        int r = ((i >> 2) << 5) + r_off;
        float4 v = *(const float4*)&stg[c * SLD + r];
        *(float4*)(out + (size_t)(colBase + c) * NPTS + rowBase + r) = v;
    }
}

// permute a loaded float4 (k = 4f..4f+3) into the paired-k quad for this thread
__device__ __forceinline__ uint4 perm_quad(float4 v, int kh) {
    float sA = kh ? v.x : v.z;
    float sB = kh ? v.y : v.w;
    float rA = __shfl_xor_sync(0xffffffffu, sA, 1);
    float rB = __shfl_xor_sync(0xffffffffu, sB, 1);
    uint4 q;
    if (kh == 0) {
        q.x = to_tf32(v.x); q.y = to_tf32(rA); q.z = to_tf32(v.y); q.w = to_tf32(rB);
    } else {
        q.x = to_tf32(rA);  q.y = to_tf32(v.z); q.z = to_tf32(rB); q.w = to_tf32(v.w);
    }
    return q;
}

__global__ __launch_bounds__(256, 2)
void rbf_fused_kernel(const float* __restrict__ X, float* __restrict__ out) {
    extern __shared__ float smem[];
    float* As  = smem;                  // [128][64] swizzled
    float* B1s = smem + 8192;
    float* B2s = smem + 16384;
    float* stg = smem + 8192;           // aliases B1s+B2s (+512 extra floats)
    __shared__ float sqa[128], sqb1[128], sqb2[128];
    __shared__ float red[256];
    __shared__ float colp[8][64];
    __shared__ float s_c;
    __shared__ int   s_last;

    const int tid = threadIdx.x;
    const int wid = tid >> 5, lane = tid & 31;
    const int bid = blockIdx.x;

    // pair-tile decode: bid -> (bi, p); tiles (bi, 2p) [if valid] and (bi, 2p+1)
    int bi = 0, rr = bid;
    while (rr >= 16 - (bi >> 1)) { rr -= 16 - (bi >> 1); bi++; }
    const int p = (bi >> 1) + rr;
    const bool two = (2 * p >= bi);
    const int bj1 = two ? 2 * p : 2 * p + 1;
    const int bj2 = 2 * p + 1;
    const bool diag1 = (bj1 == bi);
    const int rowBase = bi << 7, colBase1 = bj1 << 7, colBase2 = bj2 << 7;

    // ================= phase 0: bandwidth reduction duty (bid < 64) =================
    if (bid < 64) {
        const int rrow = (bid << 6) + (tid >> 2);
        const int q = tid & 3;
        float v[16];
        const float4* pp = (const float4*)(X + (size_t)rrow * DDIM + q * 16);
        float s = 0.f;
#pragma unroll
        for (int i = 0; i < 4; i++) {
            float4 f = pp[i];
            v[i * 4 + 0] = f.x; v[i * 4 + 1] = f.y; v[i * 4 + 2] = f.z; v[i * 4 + 3] = f.w;
            s += f.x * f.x + f.y * f.y + f.z * f.z + f.w * f.w;
        }
        red[tid] = s;
        __syncthreads();
#pragma unroll
        for (int off = 128; off > 0; off >>= 1) {
            if (tid < off) red[tid] += red[tid + off];
            __syncthreads();
        }
        if (tid == 0) g_partial_sq[bid] = red[0];
#pragma unroll
        for (int stp = 4; stp <= 16; stp <<= 1)
#pragma unroll
            for (int i = 0; i < 16; i++)
                v[i] += __shfl_xor_sync(0xffffffffu, v[i], stp);
        if (lane < 4) {
#pragma unroll
            for (int i = 0; i < 16; i++) colp[wid][lane * 16 + i] = v[i];
        }
        __syncthreads();
        if (tid < 64) {
            float t = 0.f;
#pragma unroll
            for (int w = 0; w < 8; w++) t += colp[w][tid];
            g_partial_col[bid][tid] = t;
        }
        __threadfence();
        if (tid == 0) {
            int r = atomicAdd(&g_arrive, 1);
            s_last = (r == 63);
        }
        __syncthreads();
        if (s_last) {
            if (tid < 64) {
                float cs = 0.f;
#pragma unroll
                for (int b = 0; b < 64; b++) cs += g_partial_col[b][tid];
                red[tid] = cs * cs;
                red[128 + tid] = g_partial_sq[tid];
            }
            __syncthreads();
#pragma unroll
            for (int off = 32; off > 0; off >>= 1) {
                if (tid < off) { red[tid] += red[tid + off]; red[128 + tid] += red[128 + tid + off]; }
                __syncthreads();
            }
            if (tid == 0) {
                // sum(L2) = 2*N*sum(||xi||^2) - 2*||sum xi||^2 (clamp negligible)
                float bwsum = 2.f * (float)NPTS * red[128] - 2.f * red[0];
                float bw = bwsum / ((float)NPTS * (float)(NPTS - 1));
                g_c = 1.4426950408889634f / (4.f * bw);
                __threadfence();
                asm volatile("st.release.gpu.b32 [%0], %1;" :: "l"(&g_flag), "r"(1u) : "memory");
            }
        }
        __syncthreads();
    }

    // ================= phase 1: fill A + B1 tiles (paired-k tf32) + norms =================
#pragma unroll
    for (int i = 0; i < 8; i++) {
        int idx = tid + (i << 8);
        int r = idx >> 4, f = idx & 15;
        float4 va = *(const float4*)(X + (size_t)(rowBase + r) * DDIM + (f << 2));
        float4 vb = *(const float4*)(X + (size_t)(colBase1 + r) * DDIM + (f << 2));
        float da = va.x * va.x + va.y * va.y + va.z * va.z + va.w * va.w;
        float db = vb.x * vb.x + vb.y * vb.y + vb.z * vb.z + vb.w * vb.w;
#pragma unroll
        for (int stp = 1; stp <= 8; stp <<= 1) {
            da += __shfl_xor_sync(0xffffffffu, da, stp);
            db += __shfl_xor_sync(0xffffffffu, db, stp);
        }
        if ((lane & 15) == 0) { sqa[r] = da; sqb1[r] = db; }
        const int kh = f & 1;
        uint4 qa = perm_quad(va, kh);
        uint4 qb = perm_quad(vb, kh);
        const int off = r * 64 + (((f << 2)) ^ ((r & 3) << 3));
        *(uint4*)(As + off) = qa;
        *(uint4*)(B1s + off) = qb;
    }
    __syncthreads();

    // ================= phase 2: MMA tile 1 =================
    const int g = lane >> 2, t = lane & 3;
    const int warpRow = (wid & 3) << 5;
    const int warpCol = (wid >> 2) << 6;

    float acc[2][8][4];
    mma_tile(As, B1s, warpRow, warpCol, g, t, acc);

    // prefetch B2 into registers (latency hides under spin + epilogue1)
    float4 pb[8];
    if (two) {
#pragma unroll
        for (int i = 0; i < 8; i++) {
            int idx = tid + (i << 8);
            int r = idx >> 4, f = idx & 15;
            pb[i] = *(const float4*)(X + (size_t)(colBase2 + r) * DDIM + (f << 2));
        }
    }

    // ================= phase 3: wait for g_c (usually already set) =================
    if (tid == 0) {
        unsigned int f;
        do {
            asm volatile("ld.acquire.gpu.b32 %0, [%1];" : "=r"(f) : "l"(&g_flag) : "memory");
        } while (f == 0);
        s_c = g_c;
    }
    __syncthreads();   // also: all MMA1 reads complete before stg writes
    const float cc = s_c;

    // ================= phase 4: epilogue tile 1 (+ mirror if offdiag) =================
    epilogue_tile(acc, sqa, sqb1, cc, out, rowBase, colBase1,
                  warpRow, warpCol, g, t, !diag1, stg);
    if (!diag1) {
        __syncthreads();
        mirror_tile(stg, out, rowBase, colBase1, wid, lane);
    }

    // ================= phase 5: tile 2 =================
    if (two) {
        __syncthreads();   // mirror1 stg reads done before B2s overwrite
#pragma unroll
        for (int i = 0; i < 8; i++) {
            int idx = tid + (i << 8);
            int r = idx >> 4, f = idx & 15;
            float4 vb = pb[i];
            float db = vb.x * vb.x + vb.y * vb.y + vb.z * vb.z + vb.w * vb.w;
#pragma unroll
            for (int stp = 1; stp <= 8; stp <<= 1)
                db += __shfl_xor_sync(0xffffffffu, db, stp);
            if ((lane & 15) == 0) sqb2[r] = db;
            const int kh = f & 1;
            uint4 qb = perm_quad(vb, kh);
            const int off = r * 64 + (((f << 2)) ^ ((r & 3) << 3));
            *(uint4*)(B2s + off) = qb;
        }
        __syncthreads();

        mma_tile(As, B2s, warpRow, warpCol, g, t, acc);
        __syncthreads();   // all B2s reads complete before stg writes

        epilogue_tile(acc, sqa, sqb2, cc, out, rowBase, colBase2,
                      warpRow, warpCol, g, t, true, stg);
        __syncthreads();
        mirror_tile(stg, out, rowBase, colBase2, wid, lane);
    }

    // ================= phase 6: last CTA resets counters for next replay =================
    if (tid == 0) {
        int d = atomicAdd(&g_done, 1);
        if (d == NBLOCKS - 1) {
            g_arrive = 0;
            g_done = 0;
            asm volatile("st.relaxed.gpu.b32 [%0], %1;" :: "l"(&g_flag), "r"(0u) : "memory");
        }
    }
}

// ---------------- launch ----------------
extern "C" void kernel_launch(void* const* d_in, const int* in_sizes, int n_in,
                              void* d_out, int out_size) {
    const float* X = (const float*)d_in[0];
    float* out = (float*)d_out;

    const int smem_bytes = (8192 + 16896) * sizeof(float);   // 100352
    cudaFuncSetAttribute(rbf_fused_kernel, cudaFuncAttributeMaxDynamicSharedMemorySize, smem_bytes);

    rbf_fused_kernel<<<NBLOCKS, 256, smem_bytes>>>(X, out);
}

// round 11
// speedup vs baseline: 1.2252x; 1.2226x over previous
#include <cuda_runtime.h>
#include <cstdint>

#define NPTS 4096
#define DDIM 64
#define KPW 36      // bf16 tile stride in uint32 kpairs: banks 4g+t conflict-free
#define SLD 132     // staging stride: conflict-free transpose staging (banks 8t+g)
#define NBLOCKS 272 // pair-tile blocks

// ---------------- device scratch (zero-init; counters self-reset) ----------------
__device__ float g_partial_sq[64];
__device__ float g_partial_col[64][64];
__device__ float g_c;
__device__ int   g_arrive = 0;
__device__ int   g_done   = 0;
__device__ unsigned int g_flag = 0;

// pack two consecutive-k floats into bf16x2 (lo = even k, hi = odd k)
__device__ __forceinline__ uint32_t bf2(float lo, float hi) {
    uint32_t o;
    asm("cvt.rn.bf16x2.f32 %0, %1, %2;" : "=r"(o) : "f"(hi), "f"(lo));
    return o;
}

// ---- bf16 m16n8k16 mma over one 128x128 tile; tiles [128][KPW] uint32 kpairs ----
__device__ __forceinline__ void mma_tile(const uint32_t* As, const uint32_t* Bs,
                                         int warpRow, int warpCol, int g, int t,
                                         float acc[2][8][4]) {
#pragma unroll
    for (int m = 0; m < 2; m++)
#pragma unroll
        for (int n = 0; n < 8; n++)
#pragma unroll
            for (int j = 0; j < 4; j++) acc[m][n][j] = 0.f;
#pragma unroll
    for (int s = 0; s < 4; s++) {        // K=64 in 4 k16 steps
        const int kp = (s << 3) + t;     // kpair base
        uint32_t af[2][4], bf[8][2];
#pragma unroll
        for (int m = 0; m < 2; m++) {
            const uint32_t* ap = As + (size_t)(warpRow + (m << 4) + g) * KPW + kp;
            af[m][0] = ap[0];            // (r,   k 2t..2t+1)
            af[m][1] = ap[8 * KPW];      // (r+8, k 2t..2t+1)
            af[m][2] = ap[4];            // (r,   k 2t+8..+9)
            af[m][3] = ap[8 * KPW + 4];  // (r+8, k 2t+8..+9)
        }
#pragma unroll
        for (int n = 0; n < 8; n++) {
            const uint32_t* bp = Bs + (size_t)(warpCol + (n << 3) + g) * KPW + kp;
            bf[n][0] = bp[0];
            bf[n][1] = bp[4];
        }
#pragma unroll
        for (int m = 0; m < 2; m++)
#pragma unroll
            for (int n = 0; n < 8; n++) {
                asm volatile(
                    "mma.sync.aligned.m16n8k16.row.col.f32.bf16.bf16.f32 "
                    "{%0,%1,%2,%3}, {%4,%5,%6,%7}, {%8,%9}, {%0,%1,%2,%3};"
                    : "+f"(acc[m][n][0]), "+f"(acc[m][n][1]),
                      "+f"(acc[m][n][2]), "+f"(acc[m][n][3])
                    : "r"(af[m][0]), "r"(af[m][1]), "r"(af[m][2]), "r"(af[m][3]),
                      "r"(bf[n][0]), "r"(bf[n][1]));
            }
    }
}

__device__ __forceinline__ void epilogue_tile(float acc[2][8][4],
                                              const float* sqa, const float* sqb,
                                              float cc, float* out,
                                              int rowBase, int colBase,
                                              int warpRow, int warpCol, int g, int t,
                                              bool stage, float* stg) {
    const float c2 = 2.f * cc;
#pragma unroll
    for (int m = 0; m < 2; m++) {
        const int r0 = warpRow + (m << 4) + g;
        const float u0 = -cc * sqa[r0], u1 = -cc * sqa[r0 + 8];
#pragma unroll
        for (int n = 0; n < 8; n++) {
            const int c0 = warpCol + (n << 3) + (t << 1);
            const float v0 = -cc * sqb[c0], v1 = -cc * sqb[c0 + 1];
            const float ws[4] = { u0 + v0, u0 + v1, u1 + v0, u1 + v1 };
            float r[4];
#pragma unroll
            for (int j = 0; j < 4; j++) {
                float y = fminf(fmaf(c2, acc[m][n][j], ws[j]), 0.f);
                float e;
                asm("ex2.approx.ftz.f32 %0, %1;" : "=f"(e) : "f"(y));
                float e2 = e * e, e4 = e2 * e2, e8 = e4 * e4, e16 = e8 * e8;
                r[j] = e + e2 + e4 + e8 + e16;
            }
            float* o0 = out + (size_t)(rowBase + r0) * NPTS + colBase + c0;
            float* o1 = out + (size_t)(rowBase + r0 + 8) * NPTS + colBase + c0;
            *(float2*)o0 = make_float2(r[0], r[1]);
            *(float2*)o1 = make_float2(r[2], r[3]);
            if (stage) {
                stg[(c0)     * SLD + r0]     = r[0];
                stg[(c0 + 1) * SLD + r0]     = r[1];
                stg[(c0)     * SLD + r0 + 8] = r[2];
                stg[(c0 + 1) * SLD + r0 + 8] = r[3];
            }
        }
    }
}

__device__ __forceinline__ void mirror_tile(const float* stg, float* out,
                                            int rowBase, int colBase,
                                            int wid, int lane) {
    const int c_off = lane >> 3, r_off = (lane & 7) << 2;
#pragma unroll
    for (int i = 0; i < 16; i++) {
        int c = (wid << 4) + ((i & 3) << 2) + c_off;
        int r = ((i >> 2) << 5) + r_off;
        float4 v = *(const float4*)&stg[c * SLD + r];
        *(float4*)(out + (size_t)(colBase + c) * NPTS + rowBase + r) = v;
    }
}

// smem word layout (uint32 units):
//   As  @ 0      .. 4608
//   B1s @ 4608   .. 9216
//   B2s @ 9216   .. 13824
//   stg @ 4608   .. 21504  (floats; aliases B1s+B2s region, used only when safe)
__global__ __launch_bounds__(256, 2)
void rbf_fused_kernel(const float* __restrict__ X, float* __restrict__ out) {
    extern __shared__ uint32_t smw[];
    uint32_t* As  = smw;
    uint32_t* B1s = smw + 4608;
    uint32_t* B2s = smw + 9216;
    float*    stg = (float*)(smw + 4608);
    __shared__ float sqa[128], sqb1[128], sqb2[128];
    __shared__ float red[256];
    __shared__ float colp[8][64];
    __shared__ float s_c;
    __shared__ int   s_last;

    const int tid = threadIdx.x;
    const int wid = tid >> 5, lane = tid & 31;
    const int bid = blockIdx.x;

    // pair-tile decode: bid -> (bi, p); tiles (bi, 2p) [if valid] and (bi, 2p+1)
    int bi = 0, rr = bid;
    while (rr >= 16 - (bi >> 1)) { rr -= 16 - (bi >> 1); bi++; }
    const int p = (bi >> 1) + rr;
    const bool two = (2 * p >= bi);
    const int bj1 = two ? 2 * p : 2 * p + 1;
    const int bj2 = 2 * p + 1;
    const bool diag1 = (bj1 == bi);
    const int rowBase = bi << 7, colBase1 = bj1 << 7, colBase2 = bj2 << 7;

    // ================= phase 0: bandwidth reduction duty (bid < 64) =================
    if (bid < 64) {
        const int rrow = (bid << 6) + (tid >> 2);
        const int q = tid & 3;
        float v[16];
        const float4* pp = (const float4*)(X + (size_t)rrow * DDIM + q * 16);
        float s = 0.f;
#pragma unroll
        for (int i = 0; i < 4; i++) {
            float4 f = pp[i];
            v[i * 4 + 0] = f.x; v[i * 4 + 1] = f.y; v[i * 4 + 2] = f.z; v[i * 4 + 3] = f.w;
            s += f.x * f.x + f.y * f.y + f.z * f.z + f.w * f.w;
        }
        red[tid] = s;
        __syncthreads();
#pragma unroll
        for (int off = 128; off > 0; off >>= 1) {
            if (tid < off) red[tid] += red[tid + off];
            __syncthreads();
        }
        if (tid == 0) g_partial_sq[bid] = red[0];
#pragma unroll
        for (int stp = 4; stp <= 16; stp <<= 1)
#pragma unroll
            for (int i = 0; i < 16; i++)
                v[i] += __shfl_xor_sync(0xffffffffu, v[i], stp);
        if (lane < 4) {
#pragma unroll
            for (int i = 0; i < 16; i++) colp[wid][lane * 16 + i] = v[i];
        }
        __syncthreads();
        if (tid < 64) {
            float t = 0.f;
#pragma unroll
            for (int w = 0; w < 8; w++) t += colp[w][tid];
            g_partial_col[bid][tid] = t;
        }
        __threadfence();
        if (tid == 0) {
            int r = atomicAdd(&g_arrive, 1);
            s_last = (r == 63);
        }
        __syncthreads();
        if (s_last) {
            if (tid < 64) {
                float cs = 0.f;
#pragma unroll
                for (int b = 0; b < 64; b++) cs += g_partial_col[b][tid];
                red[tid] = cs * cs;
                red[128 + tid] = g_partial_sq[tid];
            }
            __syncthreads();
#pragma unroll
            for (int off = 32; off > 0; off >>= 1) {
                if (tid < off) { red[tid] += red[tid + off]; red[128 + tid] += red[128 + tid + off]; }
                __syncthreads();
            }
            if (tid == 0) {
                // sum(L2) = 2*N*sum(||xi||^2) - 2*||sum xi||^2 (clamp negligible)
                float bwsum = 2.f * (float)NPTS * red[128] - 2.f * red[0];
                float bw = bwsum / ((float)NPTS * (float)(NPTS - 1));
                g_c = 1.4426950408889634f / (4.f * bw);
                __threadfence();
                asm volatile("st.release.gpu.b32 [%0], %1;" :: "l"(&g_flag), "r"(1u) : "memory");
            }
        }
        __syncthreads();
    }

    // ================= phase 1: fill A + B1 tiles (bf16 kpairs) + norms =================
#pragma unroll
    for (int i = 0; i < 8; i++) {
        int idx = tid + (i << 8);
        int r = idx >> 4, f = idx & 15;
        float4 va = *(const float4*)(X + (size_t)(rowBase + r) * DDIM + (f << 2));
        float4 vb = *(const float4*)(X + (size_t)(colBase1 + r) * DDIM + (f << 2));
        float da = va.x * va.x + va.y * va.y + va.z * va.z + va.w * va.w;
        float db = vb.x * vb.x + vb.y * vb.y + vb.z * vb.z + vb.w * vb.w;
#pragma unroll
        for (int stp = 1; stp <= 8; stp <<= 1) {
            da += __shfl_xor_sync(0xffffffffu, da, stp);
            db += __shfl_xor_sync(0xffffffffu, db, stp);
        }
        if ((lane & 15) == 0) { sqa[r] = da; sqb1[r] = db; }
        const int off = r * KPW + (f << 1);
        *(uint2*)(As + off)  = make_uint2(bf2(va.x, va.y), bf2(va.z, va.w));
        *(uint2*)(B1s + off) = make_uint2(bf2(vb.x, vb.y), bf2(vb.z, vb.w));
    }
    __syncthreads();

    // ================= phase 2: MMA tile 1 =================
    const int g = lane >> 2, t = lane & 3;
    const int warpRow = (wid & 3) << 5;
    const int warpCol = (wid >> 2) << 6;

    float acc[2][8][4];
    mma_tile(As, B1s, warpRow, warpCol, g, t, acc);

    // prefetch B2 into registers (latency hides under spin + epilogue1)
    float4 pb[8];
    if (two) {
#pragma unroll
        for (int i = 0; i < 8; i++) {
            int idx = tid + (i << 8);
            int r = idx >> 4, f = idx & 15;
            pb[i] = *(const float4*)(X + (size_t)(colBase2 + r) * DDIM + (f << 2));
        }
    }

    // ================= phase 3: wait for g_c (usually already set) =================
    if (tid == 0) {
        unsigned int f;
        do {
            asm volatile("ld.acquire.gpu.b32 %0, [%1];" : "=r"(f) : "l"(&g_flag) : "memory");
        } while (f == 0);
        s_c = g_c;
    }
    __syncthreads();   // also: all MMA1 reads complete before stg writes
    const float cc = s_c;

    // ================= phase 4: epilogue tile 1 (+ mirror if offdiag) =================
    epilogue_tile(acc, sqa, sqb1, cc, out, rowBase, colBase1,
                  warpRow, warpCol, g, t, !diag1, stg);
    if (!diag1) {
        __syncthreads();
        mirror_tile(stg, out, rowBase, colBase1, wid, lane);
    }

    // ================= phase 5: tile 2 =================
    if (two) {
        __syncthreads();   // mirror1 stg reads done before B2s overwrite
#pragma unroll
        for (int i = 0; i < 8; i++) {
            int idx = tid + (i << 8);
            int r = idx >> 4, f = idx & 15;
            float4 vb = pb[i];
            float db = vb.x * vb.x + vb.y * vb.y + vb.z * vb.z + vb.w * vb.w;
#pragma unroll
            for (int stp = 1; stp <= 8; stp <<= 1)
                db += __shfl_xor_sync(0xffffffffu, db, stp);
            if ((lane & 15) == 0) sqb2[r] = db;
            *(uint2*)(B2s + r * KPW + (f << 1)) = make_uint2(bf2(vb.x, vb.y), bf2(vb.z, vb.w));
        }
        __syncthreads();

        mma_tile(As, B2s, warpRow, warpCol, g, t, acc);
        __syncthreads();   // all B2s reads complete before stg writes

        epilogue_tile(acc, sqa, sqb2, cc, out, rowBase, colBase2,
                      warpRow, warpCol, g, t, true, stg);
        __syncthreads();
        mirror_tile(stg, out, rowBase, colBase2, wid, lane);
    }

    // ================= phase 6: last CTA resets counters for next replay =================
    if (tid == 0) {
        int d = atomicAdd(&g_done, 1);
        if (d == NBLOCKS - 1) {
            g_arrive = 0;
            g_done = 0;
            asm volatile("st.relaxed.gpu.b32 [%0], %1;" :: "l"(&g_flag), "r"(0u) : "memory");
        }
    }
}

// ---------------- launch ----------------
extern "C" void kernel_launch(void* const* d_in, const int* in_sizes, int n_in,
                              void* d_out, int out_size) {
    const float* X = (const float*)d_in[0];
    float* out = (float*)d_out;

    const int smem_bytes = 21504 * 4;   // As + (B1s|B2s|stg union) = 86016 B
    cudaFuncSetAttribute(rbf_fused_kernel, cudaFuncAttributeMaxDynamicSharedMemorySize, smem_bytes);

    rbf_fused_kernel<<<NBLOCKS, 256, smem_bytes>>>(X, out);
}

// round 12
// speedup vs baseline: 1.2439x; 1.0153x over previous
#include <cuda_runtime.h>
#include <cstdint>

#define NPTS 4096
#define DDIM 64
#define KPW 36      // bf16 tile stride in uint32 kpairs: banks 4g+t conflict-free
#define SLD 132     // staging stride: conflict-free transpose staging (banks 8t+g)
#define NBLOCKS 272 // pair-tile blocks (256 pairs + 16 diagonal singles)
#define NDUTY 16    // duty CTAs = the 16 diagonal singletons

// ---------------- device scratch (zero-init; counters self-reset) ----------------
__device__ float g_partial_sq[NDUTY];
__device__ float g_partial_col[NDUTY][64];
__device__ float g_c;
__device__ int   g_arrive = 0;
__device__ int   g_done   = 0;
__device__ unsigned int g_flag = 0;

// pack two consecutive-k floats into bf16x2 (lo = even k, hi = odd k)
__device__ __forceinline__ uint32_t bf2(float lo, float hi) {
    uint32_t o;
    asm("cvt.rn.bf16x2.f32 %0, %1, %2;" : "=r"(o) : "f"(hi), "f"(lo));
    return o;
}

// ---- bf16 m16n8k16 mma over one 128x128 tile; tiles [128][KPW] uint32 kpairs ----
__device__ __forceinline__ void mma_tile(const uint32_t* As, const uint32_t* Bs,
                                         int warpRow, int warpCol, int g, int t,
                                         float acc[2][8][4]) {
#pragma unroll
    for (int m = 0; m < 2; m++)
#pragma unroll
        for (int n = 0; n < 8; n++)
#pragma unroll
            for (int j = 0; j < 4; j++) acc[m][n][j] = 0.f;
#pragma unroll
    for (int s = 0; s < 4; s++) {        // K=64 in 4 k16 steps
        const int kp = (s << 3) + t;     // kpair base
        uint32_t af[2][4], bf[8][2];
#pragma unroll
        for (int m = 0; m < 2; m++) {
            const uint32_t* ap = As + (size_t)(warpRow + (m << 4) + g) * KPW + kp;
            af[m][0] = ap[0];            // (r,   k 2t..2t+1)
            af[m][1] = ap[8 * KPW];      // (r+8, k 2t..2t+1)
            af[m][2] = ap[4];            // (r,   k 2t+8..+9)
            af[m][3] = ap[8 * KPW + 4];  // (r+8, k 2t+8..+9)
        }
#pragma unroll
        for (int n = 0; n < 8; n++) {
            const uint32_t* bp = Bs + (size_t)(warpCol + (n << 3) + g) * KPW + kp;
            bf[n][0] = bp[0];
            bf[n][1] = bp[4];
        }
#pragma unroll
        for (int m = 0; m < 2; m++)
#pragma unroll
            for (int n = 0; n < 8; n++) {
                asm volatile(
                    "mma.sync.aligned.m16n8k16.row.col.f32.bf16.bf16.f32 "
                    "{%0,%1,%2,%3}, {%4,%5,%6,%7}, {%8,%9}, {%0,%1,%2,%3};"
                    : "+f"(acc[m][n][0]), "+f"(acc[m][n][1]),
                      "+f"(acc[m][n][2]), "+f"(acc[m][n][3])
                    : "r"(af[m][0]), "r"(af[m][1]), "r"(af[m][2]), "r"(af[m][3]),
                      "r"(bf[n][0]), "r"(bf[n][1]));
            }
    }
}

__device__ __forceinline__ void epilogue_tile(float acc[2][8][4],
                                              const float* sqa, const float* sqb,
                                              float cc, float* out,
                                              int rowBase, int colBase,
                                              int warpRow, int warpCol, int g, int t,
                                              bool stage, float* stg) {
    const float c2 = 2.f * cc;
#pragma unroll
    for (int m = 0; m < 2; m++) {
        const int r0 = warpRow + (m << 4) + g;
        const float u0 = -cc * sqa[r0], u1 = -cc * sqa[r0 + 8];
#pragma unroll
        for (int n = 0; n < 8; n++) {
            const int c0 = warpCol + (n << 3) + (t << 1);
            const float v0 = -cc * sqb[c0], v1 = -cc * sqb[c0 + 1];
            const float ws[4] = { u0 + v0, u0 + v1, u1 + v0, u1 + v1 };
            float r[4];
#pragma unroll
            for (int j = 0; j < 4; j++) {
                float y = fminf(fmaf(c2, acc[m][n][j], ws[j]), 0.f);
                float e;
                asm("ex2.approx.ftz.f32 %0, %1;" : "=f"(e) : "f"(y));
                float e2 = e * e;
                float s = e + e2;
                s = fmaf(e2, e2, s);          // + e^4
                float e4 = e2 * e2;
                s = fmaf(e4, e4, s);          // + e^8
                float e8 = e4 * e4;
                s = fmaf(e8, e8, s);          // + e^16
                r[j] = s;
            }
            float* o0 = out + (size_t)(rowBase + r0) * NPTS + colBase + c0;
            float* o1 = out + (size_t)(rowBase + r0 + 8) * NPTS + colBase + c0;
            *(float2*)o0 = make_float2(r[0], r[1]);
            *(float2*)o1 = make_float2(r[2], r[3]);
            if (stage) {
                stg[(c0)     * SLD + r0]     = r[0];
                stg[(c0 + 1) * SLD + r0]     = r[1];
                stg[(c0)     * SLD + r0 + 8] = r[2];
                stg[(c0 + 1) * SLD + r0 + 8] = r[3];
            }
        }
    }
}

__device__ __forceinline__ void mirror_tile(const float* stg, float* out,
                                            int rowBase, int colBase,
                                            int wid, int lane) {
    const int c_off = lane >> 3, r_off = (lane & 7) << 2;
#pragma unroll
    for (int i = 0; i < 16; i++) {
        int c = (wid << 4) + ((i & 3) << 2) + c_off;
        int r = ((i >> 2) << 5) + r_off;
        float4 v = *(const float4*)&stg[c * SLD + r];
        *(float4*)(out + (size_t)(colBase + c) * NPTS + rowBase + r) = v;
    }
}

// smem word layout (uint32 units):
//   As  @ 0      .. 4608
//   B1s @ 4608   .. 9216
//   B2s @ 9216   .. 13824
//   stg @ 4608   .. 21504  (floats; aliases B1s+B2s region, used only when safe)
__global__ __launch_bounds__(256, 2)
void rbf_fused_kernel(const float* __restrict__ X, float* __restrict__ out) {
    extern __shared__ uint32_t smw[];
    uint32_t* As  = smw;
    uint32_t* B1s = smw + 4608;
    uint32_t* B2s = smw + 9216;
    float*    stg = (float*)(smw + 4608);
    __shared__ float sqa[128], sqb1[128], sqb2[128];
    __shared__ float red[256];
    __shared__ float colp[8][64];
    __shared__ float s_c;
    __shared__ int   s_last;

    const int tid = threadIdx.x;
    const int wid = tid >> 5, lane = tid & 31;
    const int bid = blockIdx.x;

    // pair-tile decode: bid -> (bi, p); tiles (bi, 2p) [if valid] and (bi, 2p+1)
    int bi = 0, rr = bid;
    while (rr >= 16 - (bi >> 1)) { rr -= 16 - (bi >> 1); bi++; }
    const int p = (bi >> 1) + rr;
    const bool two = (2 * p >= bi);
    const int bj1 = two ? 2 * p : 2 * p + 1;
    const int bj2 = 2 * p + 1;
    const bool diag1 = (bj1 == bi);
    const int rowBase = bi << 7, colBase1 = bj1 << 7, colBase2 = bj2 << 7;

    // ===== phase 0: bandwidth duty on the 16 single-tile (diagonal) CTAs =====
    // duty CTA covers 256 rows; thread = quarter-row (16 floats) of 4 row-batches
    if (!two) {
        const int duty = bi >> 1;               // 0..15 (bi odd)
        const int base = duty << 8;             // 256 rows
        const int q = tid & 3;
        float v[16];
#pragma unroll
        for (int i = 0; i < 16; i++) v[i] = 0.f;
        float s = 0.f;
#pragma unroll
        for (int b = 0; b < 4; b++) {
            const int row = base + (b << 6) + (tid >> 2);
            const float4* pp = (const float4*)(X + (size_t)row * DDIM + q * 16);
#pragma unroll
            for (int i = 0; i < 4; i++) {
                float4 f = pp[i];
                v[i * 4 + 0] += f.x; v[i * 4 + 1] += f.y;
                v[i * 4 + 2] += f.z; v[i * 4 + 3] += f.w;
                s += f.x * f.x + f.y * f.y + f.z * f.z + f.w * f.w;
            }
        }
        red[tid] = s;
        __syncthreads();
#pragma unroll
        for (int off = 128; off > 0; off >>= 1) {
            if (tid < off) red[tid] += red[tid + off];
            __syncthreads();
        }
        if (tid == 0) g_partial_sq[duty] = red[0];
        // column partials: butterfly over the 16 row-threads sharing a quarter
#pragma unroll
        for (int stp = 4; stp <= 16; stp <<= 1)
#pragma unroll
            for (int i = 0; i < 16; i++)
                v[i] += __shfl_xor_sync(0xffffffffu, v[i], stp);
        if (lane < 4) {
#pragma unroll
            for (int i = 0; i < 16; i++) colp[wid][lane * 16 + i] = v[i];
        }
        __syncthreads();
        if (tid < 64) {
            float t = 0.f;
#pragma unroll
            for (int w = 0; w < 8; w++) t += colp[w][tid];
            g_partial_col[duty][tid] = t;
        }
        __threadfence();
        if (tid == 0) {
            int r = atomicAdd(&g_arrive, 1);
            s_last = (r == NDUTY - 1);
        }
        __syncthreads();
        if (s_last) {
            if (tid < 64) {
                float cs = 0.f;
#pragma unroll
                for (int b = 0; b < NDUTY; b++) cs += g_partial_col[b][tid];
                red[tid] = cs * cs;
                red[128 + tid] = (tid < NDUTY) ? g_partial_sq[tid] : 0.f;
            }
            __syncthreads();
#pragma unroll
            for (int off = 32; off > 0; off >>= 1) {
                if (tid < off) { red[tid] += red[tid + off]; red[128 + tid] += red[128 + tid + off]; }
                __syncthreads();
            }
            if (tid == 0) {
                // sum(L2) = 2*N*sum(||xi||^2) - 2*||sum xi||^2 (clamp negligible)
                float bwsum = 2.f * (float)NPTS * red[128] - 2.f * red[0];
                float bw = bwsum / ((float)NPTS * (float)(NPTS - 1));
                g_c = 1.4426950408889634f / (4.f * bw);
                __threadfence();
                asm volatile("st.release.gpu.b32 [%0], %1;" :: "l"(&g_flag), "r"(1u) : "memory");
            }
        }
        __syncthreads();
    }

    // ================= phase 1: fill A + B1 tiles (bf16 kpairs) + norms =================
#pragma unroll
    for (int i = 0; i < 8; i++) {
        int idx = tid + (i << 8);
        int r = idx >> 4, f = idx & 15;
        float4 va = *(const float4*)(X + (size_t)(rowBase + r) * DDIM + (f << 2));
        float4 vb = *(const float4*)(X + (size_t)(colBase1 + r) * DDIM + (f << 2));
        float da = va.x * va.x + va.y * va.y + va.z * va.z + va.w * va.w;
        float db = vb.x * vb.x + vb.y * vb.y + vb.z * vb.z + vb.w * vb.w;
#pragma unroll
        for (int stp = 1; stp <= 8; stp <<= 1) {
            da += __shfl_xor_sync(0xffffffffu, da, stp);
            db += __shfl_xor_sync(0xffffffffu, db, stp);
        }
        if ((lane & 15) == 0) { sqa[r] = da; sqb1[r] = db; }
        const int off = r * KPW + (f << 1);
        *(uint2*)(As + off)  = make_uint2(bf2(va.x, va.y), bf2(va.z, va.w));
        *(uint2*)(B1s + off) = make_uint2(bf2(vb.x, vb.y), bf2(vb.z, vb.w));
    }
    __syncthreads();

    // ================= phase 2: MMA tile 1 =================
    const int g = lane >> 2, t = lane & 3;
    const int warpRow = (wid & 3) << 5;
    const int warpCol = (wid >> 2) << 6;

    float acc[2][8][4];
    mma_tile(As, B1s, warpRow, warpCol, g, t, acc);

    // prefetch B2 into registers (latency hides under spin + epilogue1)
    float4 pb[8];
    if (two) {
#pragma unroll
        for (int i = 0; i < 8; i++) {
            int idx = tid + (i << 8);
            int r = idx >> 4, f = idx & 15;
            pb[i] = *(const float4*)(X + (size_t)(colBase2 + r) * DDIM + (f << 2));
        }
    }

    // ================= phase 3: wait for g_c (usually already set) =================
    if (tid == 0) {
        unsigned int f;
        do {
            asm volatile("ld.acquire.gpu.b32 %0, [%1];" : "=r"(f) : "l"(&g_flag) : "memory");
        } while (f == 0);
        s_c = g_c;
    }
    __syncthreads();   // also: all MMA1 reads complete before stg writes
    const float cc = s_c;

    // ================= phase 4: epilogue tile 1 (+ mirror if offdiag) =================
    epilogue_tile(acc, sqa, sqb1, cc, out, rowBase, colBase1,
                  warpRow, warpCol, g, t, !diag1, stg);
    if (!diag1) {
        __syncthreads();
        mirror_tile(stg, out, rowBase, colBase1, wid, lane);
    }

    // ================= phase 5: tile 2 =================
    if (two) {
        __syncthreads();   // mirror1 stg reads done before B2s overwrite
#pragma unroll
        for (int i = 0; i < 8; i++) {
            int idx = tid + (i << 8);
            int r = idx >> 4, f = idx & 15;
            float4 vb = pb[i];
            float db = vb.x * vb.x + vb.y * vb.y + vb.z * vb.z + vb.w * vb.w;
#pragma unroll
            for (int stp = 1; stp <= 8; stp <<= 1)
                db += __shfl_xor_sync(0xffffffffu, db, stp);
            if ((lane & 15) == 0) sqb2[r] = db;
            *(uint2*)(B2s + r * KPW + (f << 1)) = make_uint2(bf2(vb.x, vb.y), bf2(vb.z, vb.w));
        }
        __syncthreads();

        mma_tile(As, B2s, warpRow, warpCol, g, t, acc);
        __syncthreads();   // all B2s reads complete before stg writes

        epilogue_tile(acc, sqa, sqb2, cc, out, rowBase, colBase2,
                      warpRow, warpCol, g, t, true, stg);
        __syncthreads();
        mirror_tile(stg, out, rowBase, colBase2, wid, lane);
    }

    // ================= phase 6: last CTA resets counters for next replay =================
    if (tid == 0) {
        int d = atomicAdd(&g_done, 1);
        if (d == NBLOCKS - 1) {
            g_arrive = 0;
            g_done = 0;
            asm volatile("st.relaxed.gpu.b32 [%0], %1;" :: "l"(&g_flag), "r"(0u) : "memory");
        }
    }
}

// ---------------- launch ----------------
extern "C" void kernel_launch(void* const* d_in, const int* in_sizes, int n_in,
                              void* d_out, int out_size) {
    const float* X = (const float*)d_in[0];
    float* out = (float*)d_out;

    const int smem_bytes = 21504 * 4;   // As + (B1s|B2s|stg union) = 86016 B
    cudaFuncSetAttribute(rbf_fused_kernel, cudaFuncAttributeMaxDynamicSharedMemorySize, smem_bytes);

    rbf_fused_kernel<<<NBLOCKS, 256, smem_bytes>>>(X, out);
}